// round 2
// baseline (speedup 1.0000x reference)
#include <cuda_runtime.h>
#include <cstdint>

#define NB    4
#define NPTS  16384
#define NC    64
#define NSMP  1024      // S (npoint)
#define NNEI  32        // nsample
#define D0    67        // 3 + C
#define D1    64
#define D2    64
#define D3    128

// scratch: ball query neighbor indices
__device__ int g_ball_idx[NB * NSMP * NNEI];

// ---------------------------------------------------------------------------
// FPS: one block per batch. xyz staged in SMEM (SoA). dist[] in registers.
// Writes new_xyz (coords) directly into the first B*S*3 floats of d_out.
// ---------------------------------------------------------------------------
__global__ __launch_bounds__(1024, 1)
void fps_kernel(const float* __restrict__ xyz, float* __restrict__ out_xyz) {
    extern __shared__ float sm[];
    float* sx = sm;
    float* sy = sm + NPTS;
    float* sz = sm + 2 * NPTS;
    __shared__ float s_red_v[32];
    __shared__ int   s_red_i[32];
    __shared__ float s_cur[3];

    const int b   = blockIdx.x;
    const int tid = threadIdx.x;
    const float* base = xyz + (size_t)b * NPTS * 3;

    // coalesced load -> SoA scatter into smem
    for (int k = tid; k < NPTS * 3; k += 1024) {
        float v = base[k];
        int p = k / 3, c = k - 3 * p;
        if (c == 0)      sx[p] = v;
        else if (c == 1) sy[p] = v;
        else             sz[p] = v;
    }
    __syncthreads();

    const int PT = NPTS / 1024;   // 16 points per thread
    float dist[PT];
#pragma unroll
    for (int j = 0; j < PT; j++) dist[j] = 3.4e38f;

    if (tid == 0) { s_cur[0] = sx[0]; s_cur[1] = sy[0]; s_cur[2] = sz[0]; }
    __syncthreads();

    float* oxy = out_xyz + (size_t)b * NSMP * 3;
    const int wid = tid >> 5, lane = tid & 31;

    for (int s = 0; s < NSMP; s++) {
        float cx = s_cur[0], cy = s_cur[1], cz = s_cur[2];
        if (tid == 0) {
            oxy[s * 3 + 0] = cx; oxy[s * 3 + 1] = cy; oxy[s * 3 + 2] = cz;
        }
        float bv = -1.0f; int bi = 0;
#pragma unroll
        for (int j = 0; j < PT; j++) {
            int i = tid + (j << 10);
            float dx = sx[i] - cx, dy = sy[i] - cy, dz = sz[i] - cz;
            float d  = dx * dx + dy * dy + dz * dz;
            float nd = fminf(dist[j], d);
            dist[j] = nd;
            if (nd > bv) { bv = nd; bi = i; }   // ascending i -> first-max kept
        }
        // warp argmax (tie -> smaller index, matching jnp.argmax)
#pragma unroll
        for (int off = 16; off; off >>= 1) {
            float ov = __shfl_down_sync(0xffffffffu, bv, off);
            int   oi = __shfl_down_sync(0xffffffffu, bi, off);
            if (ov > bv || (ov == bv && oi < bi)) { bv = ov; bi = oi; }
        }
        if (lane == 0) { s_red_v[wid] = bv; s_red_i[wid] = bi; }
        __syncthreads();
        if (wid == 0) {
            bv = s_red_v[lane]; bi = s_red_i[lane];
#pragma unroll
            for (int off = 16; off; off >>= 1) {
                float ov = __shfl_down_sync(0xffffffffu, bv, off);
                int   oi = __shfl_down_sync(0xffffffffu, bi, off);
                if (ov > bv || (ov == bv && oi < bi)) { bv = ov; bi = oi; }
            }
            if (lane == 0) { s_cur[0] = sx[bi]; s_cur[1] = sy[bi]; s_cur[2] = sz[bi]; }
        }
        __syncthreads();
    }
}

// ---------------------------------------------------------------------------
// Ball query: one warp per centroid. Collect first NNEI indices (scan order)
// with d2 <= r^2; pad remaining slots with the first hit. Early exit.
// ---------------------------------------------------------------------------
__global__ void ball_kernel(const float* __restrict__ xyz,
                            const float* __restrict__ new_xyz) {
    const int gw   = (blockIdx.x * blockDim.x + threadIdx.x) >> 5;
    const int lane = threadIdx.x & 31;
    if (gw >= NB * NSMP) return;
    const int b = gw >> 10;
    const float* base = xyz + (size_t)b * NPTS * 3;
    const float cx = new_xyz[gw * 3 + 0];
    const float cy = new_xyz[gw * 3 + 1];
    const float cz = new_xyz[gw * 3 + 2];
    const float r2 = 0.2f * 0.2f;
    int* out = g_ball_idx + gw * NNEI;

    int cnt = 0, first = 0;
    for (int j0 = 0; j0 < NPTS; j0 += 32) {
        const int j = j0 + lane;
        float dx = base[3 * j]     - cx;
        float dy = base[3 * j + 1] - cy;
        float dz = base[3 * j + 2] - cz;
        float d2 = dx * dx + dy * dy + dz * dz;
        bool hit = (d2 <= r2);
        unsigned m = __ballot_sync(0xffffffffu, hit);
        if (m) {
            if (cnt == 0) first = j0 + (__ffs(m) - 1);
            int pos = cnt + __popc(m & ((1u << lane) - 1u));
            if (hit && pos < NNEI) out[pos] = j;
            cnt += __popc(m);
            if (cnt >= NNEI) break;
        }
    }
    if (cnt < NNEI) {
        for (int p = cnt + lane; p < NNEI; p += 32) out[p] = first;
    }
}

// ---------------------------------------------------------------------------
// Fused grouping + 3-layer MLP + maxpool. One block (256 thr) per centroid.
// Weights staged per layer in SMEM; h buffers ping-pong in SMEM.
// ---------------------------------------------------------------------------
__global__ __launch_bounds__(256, 3)
void group_mlp_kernel(const float* __restrict__ xyz,
                      const float* __restrict__ feat,
                      const float* __restrict__ W0, const float* __restrict__ b0,
                      const float* __restrict__ W1, const float* __restrict__ b1,
                      const float* __restrict__ W2, const float* __restrict__ b2,
                      const float* __restrict__ new_xyz,
                      float* __restrict__ out_feat) {
    extern __shared__ float sm[];
    float* W    = sm;                    // up to 8192 floats
    float* bias = W + 8192;              // 128
    float* hA   = bias + 128;            // 32*67 = 2144
    float* hB   = hA + 2144;             // 32*128 = 4096
    float* hC   = hB + 4096;             // 32*64  = 2048
    __shared__ int s_ni[NNEI];

    const int cid = blockIdx.x;          // 0 .. NB*NSMP-1
    const int b   = cid >> 10;
    const int tid = threadIdx.x;

    if (tid < NNEI) s_ni[tid] = g_ball_idx[cid * NNEI + tid];
    for (int i = tid; i < D0 * D1; i += 256) W[i] = W0[i];
    if (tid < D1) bias[tid] = b0[tid];
    __syncthreads();

    const float* xb = xyz  + (size_t)b * NPTS * 3;
    const float* fb = feat + (size_t)b * NPTS * NC;

    // build h0 = [g_xyz - centroid, g_feat]
    for (int e = tid; e < NNEI * 3; e += 256) {
        int ns = e / 3, k = e - 3 * ns;
        hA[ns * D0 + k] = xb[(size_t)s_ni[ns] * 3 + k] - new_xyz[cid * 3 + k];
    }
    for (int e = tid; e < NNEI * NC; e += 256) {
        int ns = e >> 6, c = e & 63;
        hA[ns * D0 + 3 + c] = fb[(size_t)s_ni[ns] * NC + c];
    }
    __syncthreads();

    // layer 1: hA(67) -> hB(64)
    for (int o = tid; o < NNEI * D1; o += 256) {
        int ns = o >> 6, dj = o & 63;
        float acc = bias[dj];
        const float* hr = hA + ns * D0;
#pragma unroll 4
        for (int d = 0; d < D0; d++) acc = fmaf(hr[d], W[d * D1 + dj], acc);
        hB[ns * D1 + dj] = fmaxf(acc, 0.0f);
    }
    __syncthreads();

    for (int i = tid; i < D1 * D2; i += 256) W[i] = W1[i];
    if (tid < D2) bias[tid] = b1[tid];
    __syncthreads();

    // layer 2: hB(64) -> hC(64)
    for (int o = tid; o < NNEI * D2; o += 256) {
        int ns = o >> 6, dj = o & 63;
        float acc = bias[dj];
        const float* hr = hB + ns * D1;
#pragma unroll 4
        for (int d = 0; d < D1; d++) acc = fmaf(hr[d], W[d * D2 + dj], acc);
        hC[ns * D2 + dj] = fmaxf(acc, 0.0f);
    }
    __syncthreads();

    for (int i = tid; i < D2 * D3; i += 256) W[i] = W2[i];
    if (tid < D3) bias[tid] = b2[tid];
    __syncthreads();

    // layer 3: hC(64) -> hB(128)
    for (int o = tid; o < NNEI * D3; o += 256) {
        int ns = o >> 7, dj = o & 127;
        float acc = bias[dj];
        const float* hr = hC + ns * D2;
#pragma unroll 4
        for (int d = 0; d < D2; d++) acc = fmaf(hr[d], W[d * D3 + dj], acc);
        hB[ns * D3 + dj] = fmaxf(acc, 0.0f);
    }
    __syncthreads();

    // maxpool over neighbors
    for (int dj = tid; dj < D3; dj += 256) {
        float m = hB[dj];
#pragma unroll 4
        for (int ns = 1; ns < NNEI; ns++) m = fmaxf(m, hB[ns * D3 + dj]);
        out_feat[(size_t)cid * D3 + dj] = m;
    }
}

// ---------------------------------------------------------------------------
extern "C" void kernel_launch(void* const* d_in, const int* in_sizes, int n_in,
                              void* d_out, int out_size) {
    const float* xyz  = (const float*)d_in[0];
    const float* feat = (const float*)d_in[1];
    const float* W0   = (const float*)d_in[2];
    const float* b0   = (const float*)d_in[3];
    const float* W1   = (const float*)d_in[4];
    const float* b1   = (const float*)d_in[5];
    const float* W2   = (const float*)d_in[6];
    const float* b2   = (const float*)d_in[7];

    float* out      = (float*)d_out;
    float* new_xyz  = out;                       // B*S*3
    float* out_feat = out + NB * NSMP * 3;       // B*S*128

    static_assert(NPTS % 1024 == 0, "");

    const int fps_smem = NPTS * 3 * sizeof(float);               // 196608
    const int mlp_smem = (8192 + 128 + 2144 + 4096 + 2048) * 4;  // 66432
    cudaFuncSetAttribute(fps_kernel, cudaFuncAttributeMaxDynamicSharedMemorySize, fps_smem);
    cudaFuncSetAttribute(group_mlp_kernel, cudaFuncAttributeMaxDynamicSharedMemorySize, mlp_smem);

    fps_kernel<<<NB, 1024, fps_smem>>>(xyz, new_xyz);

    // one warp per centroid: NB*NSMP warps
    const int bq_threads = 256;
    const int bq_blocks  = (NB * NSMP * 32 + bq_threads - 1) / bq_threads;
    ball_kernel<<<bq_blocks, bq_threads>>>(xyz, new_xyz);

    group_mlp_kernel<<<NB * NSMP, 256, mlp_smem>>>(
        xyz, feat, W0, b0, W1, b1, W2, b2, new_xyz, out_feat);
}

// round 3
// speedup vs baseline: 1.7986x; 1.7986x over previous
#include <cuda_runtime.h>
#include <cooperative_groups.h>
#include <cstdint>

namespace cg = cooperative_groups;

#define NB    4
#define NPTS  16384
#define NC    64
#define NSMP  1024      // S (npoint)
#define NNEI  32        // nsample
#define D0    67        // 3 + C
#define D1    64
#define D2    64
#define D3    128

#define FCTAS 8                 // cluster size (CTAs per batch)
#define FTHR  256               // threads per FPS CTA
#define PPC   (NPTS / FCTAS)    // 2048 points per CTA
#define PPT   (PPC / FTHR)      // 8 points per thread

// scratch: ball query neighbor indices
__device__ int g_ball_idx[NB * NSMP * NNEI];

// ---------------------------------------------------------------------------
// FPS: one 8-CTA cluster per batch. Points register-resident per thread.
// Per step: local update+argmax -> warp reduce -> CTA reduce -> all-to-all
// DSMEM record exchange -> cluster.sync -> local 8-way reduce.
// Record buffers are double-buffered by step parity (one cluster.sync/step).
// ---------------------------------------------------------------------------
__global__ __launch_bounds__(FTHR, 1) __cluster_dims__(FCTAS, 1, 1)
void fps_cluster_kernel(const float* __restrict__ xyz, float* __restrict__ out_xyz) {
    __shared__ float  sx[PPC], sy[PPC], sz[PPC];
    __shared__ float4 s_recv[2][FCTAS];   // (val, x, y, z)
    __shared__ int    s_reci[2][FCTAS];   // global idx
    __shared__ float4 s_cur;
    __shared__ float  s_wv[FTHR / 32];
    __shared__ int    s_wi[FTHR / 32];

    cg::cluster_group cluster = cg::this_cluster();
    const int crank = cluster.block_rank();
    const int b     = blockIdx.x / FCTAS;
    const int tid   = threadIdx.x;
    const int lane  = tid & 31;
    const int wid   = tid >> 5;

    const float* base = xyz + (size_t)b * NPTS * 3;
    const int g0 = crank * PPC;

    // load this CTA's slice into smem SoA (also kept for coord lookup)
    for (int k = tid; k < PPC * 3; k += FTHR) {
        float v = base[(size_t)g0 * 3 + k];
        int p = k / 3, c = k - 3 * p;
        if (c == 0)      sx[p] = v;
        else if (c == 1) sy[p] = v;
        else             sz[p] = v;
    }
    if (tid == 0) s_cur = make_float4(base[0], base[1], base[2], 0.0f);
    __syncthreads();

    // register-resident points + distances
    float px[PPT], py[PPT], pz[PPT], dist[PPT];
#pragma unroll
    for (int j = 0; j < PPT; j++) {
        int i = tid + j * FTHR;
        px[j] = sx[i]; py[j] = sy[i]; pz[j] = sz[i];
        dist[j] = 3.4e38f;
    }

    float* oxy = out_xyz + (size_t)b * NSMP * 3;

    for (int s = 0; s < NSMP; s++) {
        const float cx = s_cur.x, cy = s_cur.y, cz = s_cur.z;
        if (crank == 0 && tid == 0) {
            oxy[s * 3 + 0] = cx; oxy[s * 3 + 1] = cy; oxy[s * 3 + 2] = cz;
        }

        // update + local argmax (thread-local indices ascending -> first max kept)
        float bv = -1.0f; int bi = 0;
#pragma unroll
        for (int j = 0; j < PPT; j++) {
            float dx = px[j] - cx, dy = py[j] - cy, dz = pz[j] - cz;
            float d  = dx * dx + dy * dy + dz * dz;
            float nd = fminf(dist[j], d);
            dist[j] = nd;
            if (nd > bv) { bv = nd; bi = tid + j * FTHR; }
        }
        // warp argmax (tie -> smaller index)
#pragma unroll
        for (int off = 16; off; off >>= 1) {
            float ov = __shfl_down_sync(0xffffffffu, bv, off);
            int   oi = __shfl_down_sync(0xffffffffu, bi, off);
            if (ov > bv || (ov == bv && oi < bi)) { bv = ov; bi = oi; }
        }
        if (lane == 0) { s_wv[wid] = bv; s_wi[wid] = bi; }
        __syncthreads();

        const int par = s & 1;
        if (wid == 0) {
            const int NW = FTHR / 32;   // 8
            bv = (lane < NW) ? s_wv[lane] : -1.0f;
            bi = (lane < NW) ? s_wi[lane] : 0x7fffffff;
#pragma unroll
            for (int off = 4; off; off >>= 1) {
                float ov = __shfl_down_sync(0xffffffffu, bv, off);
                int   oi = __shfl_down_sync(0xffffffffu, bi, off);
                if (ov > bv || (ov == bv && oi < bi)) { bv = ov; bi = oi; }
            }
            if (lane == 0) {
                float4 rec = make_float4(bv, sx[bi], sy[bi], sz[bi]);
                int gi = g0 + bi;
#pragma unroll
                for (int r = 0; r < FCTAS; r++) {
                    float4* dv = cluster.map_shared_rank(&s_recv[par][crank], r);
                    *dv = rec;
                    int* di = cluster.map_shared_rank(&s_reci[par][crank], r);
                    *di = gi;
                }
            }
        }
        cluster.sync();

        // every CTA reduces the 8 records locally (deterministic winner)
        if (wid == 0) {
            float4 rv = s_recv[par][lane & 7];
            int    ri = s_reci[par][lane & 7];
            float vv = (lane < FCTAS) ? rv.x : -1.0f;
            int   ii = (lane < FCTAS) ? ri   : 0x7fffffff;
            float X = rv.y, Y = rv.z, Z = rv.w;
#pragma unroll
            for (int off = 4; off; off >>= 1) {
                float ov = __shfl_down_sync(0xffffffffu, vv, off);
                int   oi = __shfl_down_sync(0xffffffffu, ii, off);
                float ox = __shfl_down_sync(0xffffffffu, X, off);
                float oy = __shfl_down_sync(0xffffffffu, Y, off);
                float oz = __shfl_down_sync(0xffffffffu, Z, off);
                if (ov > vv || (ov == vv && oi < ii)) { vv = ov; ii = oi; X = ox; Y = oy; Z = oz; }
            }
            if (lane == 0) s_cur = make_float4(X, Y, Z, 0.0f);
        }
        __syncthreads();
    }
}

// ---------------------------------------------------------------------------
// Ball query: one warp per centroid. Collect first NNEI indices (scan order)
// with d2 <= r^2; pad remaining slots with the first hit. Early exit.
// ---------------------------------------------------------------------------
__global__ void ball_kernel(const float* __restrict__ xyz,
                            const float* __restrict__ new_xyz) {
    const int gw   = (blockIdx.x * blockDim.x + threadIdx.x) >> 5;
    const int lane = threadIdx.x & 31;
    if (gw >= NB * NSMP) return;
    const int b = gw >> 10;
    const float* base = xyz + (size_t)b * NPTS * 3;
    const float cx = new_xyz[gw * 3 + 0];
    const float cy = new_xyz[gw * 3 + 1];
    const float cz = new_xyz[gw * 3 + 2];
    const float r2 = 0.2f * 0.2f;
    int* out = g_ball_idx + gw * NNEI;

    int cnt = 0, first = 0;
    for (int j0 = 0; j0 < NPTS; j0 += 32) {
        const int j = j0 + lane;
        float dx = base[3 * j]     - cx;
        float dy = base[3 * j + 1] - cy;
        float dz = base[3 * j + 2] - cz;
        float d2 = dx * dx + dy * dy + dz * dz;
        bool hit = (d2 <= r2);
        unsigned m = __ballot_sync(0xffffffffu, hit);
        if (m) {
            if (cnt == 0) first = j0 + (__ffs(m) - 1);
            int pos = cnt + __popc(m & ((1u << lane) - 1u));
            if (hit && pos < NNEI) out[pos] = j;
            cnt += __popc(m);
            if (cnt >= NNEI) break;
        }
    }
    if (cnt < NNEI) {
        for (int p = cnt + lane; p < NNEI; p += 32) out[p] = first;
    }
}

// ---------------------------------------------------------------------------
// Fused grouping + 3-layer MLP + maxpool. One block (256 thr) per centroid.
// Register-tiled: each thread owns 2 neighbors x 4 (or 8) channels;
// weights read as float4 from smem.
// ---------------------------------------------------------------------------
__global__ __launch_bounds__(256, 3)
void group_mlp_kernel(const float* __restrict__ xyz,
                      const float* __restrict__ feat,
                      const float* __restrict__ W0, const float* __restrict__ b0,
                      const float* __restrict__ W1, const float* __restrict__ b1,
                      const float* __restrict__ W2, const float* __restrict__ b2,
                      const float* __restrict__ new_xyz,
                      float* __restrict__ out_feat) {
    extern __shared__ float sm[];
    float* W    = sm;                    // up to 8192 floats
    float* bias = W + 8192;              // 128
    float* hA   = bias + 128;            // 32*67 = 2144
    float* hB   = hA + 2144;             // 32*128 = 4096
    float* hC   = hB + 4096;             // 32*64  = 2048
    __shared__ int s_ni[NNEI];

    const int cid = blockIdx.x;          // 0 .. NB*NSMP-1
    const int b   = cid >> 10;
    const int tid = threadIdx.x;

    if (tid < NNEI) s_ni[tid] = g_ball_idx[cid * NNEI + tid];
    for (int i = tid; i < D0 * D1; i += 256) W[i] = W0[i];
    if (tid < D1) bias[tid] = b0[tid];
    __syncthreads();

    const float* xb = xyz  + (size_t)b * NPTS * 3;
    const float* fb = feat + (size_t)b * NPTS * NC;

    // build h0 = [g_xyz - centroid, g_feat]
    for (int e = tid; e < NNEI * 3; e += 256) {
        int ns = e / 3, k = e - 3 * ns;
        hA[ns * D0 + k] = xb[(size_t)s_ni[ns] * 3 + k] - new_xyz[cid * 3 + k];
    }
    for (int e = tid; e < NNEI * NC; e += 256) {
        int ns = e >> 6, c = e & 63;
        hA[ns * D0 + 3 + c] = fb[(size_t)s_ni[ns] * NC + c];
    }
    __syncthreads();

    const int chq = tid & 15;            // channel quad index (16 quads)
    const int ns0 = (tid >> 4) * 2;      // neighbor pair

    // ---- layer 1: hA(67) -> hB(64), 2 ns x 4 ch per thread ----
    {
        float4 bs = *(float4*)&bias[chq * 4];
        float a00 = bs.x, a01 = bs.y, a02 = bs.z, a03 = bs.w;
        float a10 = bs.x, a11 = bs.y, a12 = bs.z, a13 = bs.w;
        const float* h0 = hA + ns0 * D0;
        const float* h1 = hA + (ns0 + 1) * D0;
#pragma unroll 4
        for (int d = 0; d < D0; d++) {
            float v0 = h0[d], v1 = h1[d];
            float4 w = *(float4*)&W[d * D1 + chq * 4];
            a00 = fmaf(v0, w.x, a00); a01 = fmaf(v0, w.y, a01);
            a02 = fmaf(v0, w.z, a02); a03 = fmaf(v0, w.w, a03);
            a10 = fmaf(v1, w.x, a10); a11 = fmaf(v1, w.y, a11);
            a12 = fmaf(v1, w.z, a12); a13 = fmaf(v1, w.w, a13);
        }
        *(float4*)&hB[ns0 * D1 + chq * 4] =
            make_float4(fmaxf(a00, 0.f), fmaxf(a01, 0.f), fmaxf(a02, 0.f), fmaxf(a03, 0.f));
        *(float4*)&hB[(ns0 + 1) * D1 + chq * 4] =
            make_float4(fmaxf(a10, 0.f), fmaxf(a11, 0.f), fmaxf(a12, 0.f), fmaxf(a13, 0.f));
    }
    __syncthreads();

    for (int i = tid; i < D1 * D2; i += 256) W[i] = W1[i];
    if (tid < D2) bias[tid] = b1[tid];
    __syncthreads();

    // ---- layer 2: hB(64) -> hC(64) ----
    {
        float4 bs = *(float4*)&bias[chq * 4];
        float a00 = bs.x, a01 = bs.y, a02 = bs.z, a03 = bs.w;
        float a10 = bs.x, a11 = bs.y, a12 = bs.z, a13 = bs.w;
        const float* h0 = hB + ns0 * D1;
        const float* h1 = hB + (ns0 + 1) * D1;
#pragma unroll 4
        for (int d = 0; d < D1; d++) {
            float v0 = h0[d], v1 = h1[d];
            float4 w = *(float4*)&W[d * D2 + chq * 4];
            a00 = fmaf(v0, w.x, a00); a01 = fmaf(v0, w.y, a01);
            a02 = fmaf(v0, w.z, a02); a03 = fmaf(v0, w.w, a03);
            a10 = fmaf(v1, w.x, a10); a11 = fmaf(v1, w.y, a11);
            a12 = fmaf(v1, w.z, a12); a13 = fmaf(v1, w.w, a13);
        }
        *(float4*)&hC[ns0 * D2 + chq * 4] =
            make_float4(fmaxf(a00, 0.f), fmaxf(a01, 0.f), fmaxf(a02, 0.f), fmaxf(a03, 0.f));
        *(float4*)&hC[(ns0 + 1) * D2 + chq * 4] =
            make_float4(fmaxf(a10, 0.f), fmaxf(a11, 0.f), fmaxf(a12, 0.f), fmaxf(a13, 0.f));
    }
    __syncthreads();

    for (int i = tid; i < D2 * D3; i += 256) W[i] = W2[i];
    if (tid < D3) bias[tid] = b2[tid];
    __syncthreads();

    // ---- layer 3: hC(64) -> hB(128), 2 ns x 8 ch per thread ----
    {
        const int ch8 = chq * 8;
        float4 bs0 = *(float4*)&bias[ch8];
        float4 bs1 = *(float4*)&bias[ch8 + 4];
        float a0[8] = {bs0.x, bs0.y, bs0.z, bs0.w, bs1.x, bs1.y, bs1.z, bs1.w};
        float a1[8] = {bs0.x, bs0.y, bs0.z, bs0.w, bs1.x, bs1.y, bs1.z, bs1.w};
        const float* h0 = hC + ns0 * D2;
        const float* h1 = hC + (ns0 + 1) * D2;
#pragma unroll 4
        for (int d = 0; d < D2; d++) {
            float v0 = h0[d], v1 = h1[d];
            float4 w0 = *(float4*)&W[d * D3 + ch8];
            float4 w1 = *(float4*)&W[d * D3 + ch8 + 4];
            a0[0] = fmaf(v0, w0.x, a0[0]); a0[1] = fmaf(v0, w0.y, a0[1]);
            a0[2] = fmaf(v0, w0.z, a0[2]); a0[3] = fmaf(v0, w0.w, a0[3]);
            a0[4] = fmaf(v0, w1.x, a0[4]); a0[5] = fmaf(v0, w1.y, a0[5]);
            a0[6] = fmaf(v0, w1.z, a0[6]); a0[7] = fmaf(v0, w1.w, a0[7]);
            a1[0] = fmaf(v1, w0.x, a1[0]); a1[1] = fmaf(v1, w0.y, a1[1]);
            a1[2] = fmaf(v1, w0.z, a1[2]); a1[3] = fmaf(v1, w0.w, a1[3]);
            a1[4] = fmaf(v1, w1.x, a1[4]); a1[5] = fmaf(v1, w1.y, a1[5]);
            a1[6] = fmaf(v1, w1.z, a1[6]); a1[7] = fmaf(v1, w1.w, a1[7]);
        }
        *(float4*)&hB[ns0 * D3 + ch8] =
            make_float4(fmaxf(a0[0], 0.f), fmaxf(a0[1], 0.f), fmaxf(a0[2], 0.f), fmaxf(a0[3], 0.f));
        *(float4*)&hB[ns0 * D3 + ch8 + 4] =
            make_float4(fmaxf(a0[4], 0.f), fmaxf(a0[5], 0.f), fmaxf(a0[6], 0.f), fmaxf(a0[7], 0.f));
        *(float4*)&hB[(ns0 + 1) * D3 + ch8] =
            make_float4(fmaxf(a1[0], 0.f), fmaxf(a1[1], 0.f), fmaxf(a1[2], 0.f), fmaxf(a1[3], 0.f));
        *(float4*)&hB[(ns0 + 1) * D3 + ch8 + 4] =
            make_float4(fmaxf(a1[4], 0.f), fmaxf(a1[5], 0.f), fmaxf(a1[6], 0.f), fmaxf(a1[7], 0.f));
    }
    __syncthreads();

    // maxpool over neighbors
    for (int dj = tid; dj < D3; dj += 256) {
        float m = hB[dj];
#pragma unroll 4
        for (int ns = 1; ns < NNEI; ns++) m = fmaxf(m, hB[ns * D3 + dj]);
        out_feat[(size_t)cid * D3 + dj] = m;
    }
}

// ---------------------------------------------------------------------------
extern "C" void kernel_launch(void* const* d_in, const int* in_sizes, int n_in,
                              void* d_out, int out_size) {
    const float* xyz  = (const float*)d_in[0];
    const float* feat = (const float*)d_in[1];
    const float* W0   = (const float*)d_in[2];
    const float* b0   = (const float*)d_in[3];
    const float* W1   = (const float*)d_in[4];
    const float* b1   = (const float*)d_in[5];
    const float* W2   = (const float*)d_in[6];
    const float* b2   = (const float*)d_in[7];

    float* out      = (float*)d_out;
    float* new_xyz  = out;                       // B*S*3
    float* out_feat = out + NB * NSMP * 3;       // B*S*128

    const int mlp_smem = (8192 + 128 + 2144 + 4096 + 2048) * 4;  // 66432
    cudaFuncSetAttribute(group_mlp_kernel, cudaFuncAttributeMaxDynamicSharedMemorySize, mlp_smem);

    fps_cluster_kernel<<<NB * FCTAS, FTHR>>>(xyz, new_xyz);

    const int bq_threads = 256;
    const int bq_blocks  = (NB * NSMP * 32 + bq_threads - 1) / bq_threads;
    ball_kernel<<<bq_blocks, bq_threads>>>(xyz, new_xyz);

    group_mlp_kernel<<<NB * NSMP, 256, mlp_smem>>>(
        xyz, feat, W0, b0, W1, b1, W2, b2, new_xyz, out_feat);
}